// round 2
// baseline (speedup 1.0000x reference)
#include <cuda_runtime.h>

#define BB 8
#define HH 128
#define WWD 128
#define DD 512
#define DD4 128   // D / 4

// Scratch (allocation-free rule: __device__ globals)
__device__ float4 g_partial[BB * HH * 5 * DD4];  // [b][h][k][d4], k=0..3 w-region sums, k=4 full row
__device__ float4 g_sums[BB * 17 * DD4];         // [b][r][d4], r=0..15 region sums, r=16 global

__device__ __forceinline__ float4 f4add(float4 a, float4 b) {
    return make_float4(a.x + b.x, a.y + b.y, a.z + b.z, a.w + b.w);
}
__device__ __forceinline__ float4 f4fma(float s, float4 a, float4 b) {
    return make_float4(fmaf(s, a.x, b.x), fmaf(s, a.y, b.y),
                       fmaf(s, a.z, b.z), fmaf(s, a.w, b.w));
}

// ---------------------------------------------------------------------------
// k1: per (b,h) row — accumulate per-w-region partial sums + full row sum.
// grid = B*H blocks, 128 threads (one float4 d-lane each).
// ---------------------------------------------------------------------------
__global__ __launch_bounds__(128) void k1_rowsums(const float4* __restrict__ feat) {
    const int bh = blockIdx.x;                 // b*128 + h
    const int t  = threadIdx.x;                // d4 lane
    const float4* row = feat + (size_t)bh * WWD * DD4 + t;

    float4 a0 = make_float4(0.f, 0.f, 0.f, 0.f);
    float4 a1 = a0, a2 = a0, a3 = a0, af = a0;

    #pragma unroll 4
    for (int w = 0; w < WWD; ++w) {
        float4 v = __ldg(&row[(size_t)w * DD4]);
        af = f4add(af, v);
        // region j covers w in [24j, 24j+32)
        if (w < 32)             a0 = f4add(a0, v);
        if (w >= 24 && w < 56)  a1 = f4add(a1, v);
        if (w >= 48 && w < 80)  a2 = f4add(a2, v);
        if (w >= 72 && w < 104) a3 = f4add(a3, v);
    }

    float4* p = g_partial + (size_t)bh * 5 * DD4 + t;
    p[0 * DD4] = a0;
    p[1 * DD4] = a1;
    p[2 * DD4] = a2;
    p[3 * DD4] = a3;
    p[4 * DD4] = af;
}

// ---------------------------------------------------------------------------
// k1b: reduce partials over h into 16 region sums + global sum.
// grid = B*17 blocks, 128 threads.
// ---------------------------------------------------------------------------
__global__ __launch_bounds__(128) void k1b_reduce() {
    const int b = blockIdx.x / 17;
    const int r = blockIdx.x % 17;
    const int t = threadIdx.x;

    float4 acc = make_float4(0.f, 0.f, 0.f, 0.f);
    if (r < 16) {
        const int i  = r >> 2;     // h-region index
        const int j  = r & 3;      // w-region index
        const int h0 = 24 * i;     // h-region covers [24i, 24i+32)
        #pragma unroll 8
        for (int hh = 0; hh < 32; ++hh) {
            float4 v = g_partial[((size_t)(b * HH + h0 + hh) * 5 + j) * DD4 + t];
            acc = f4add(acc, v);
        }
    } else {
        #pragma unroll 8
        for (int h = 0; h < HH; ++h) {
            float4 v = g_partial[((size_t)(b * HH + h) * 5 + 4) * DD4 + t];
            acc = f4add(acc, v);
        }
    }
    g_sums[(size_t)(b * 17 + r) * DD4 + t] = acc;
}

// ---------------------------------------------------------------------------
// k2: elementwise pass. grid = B*H blocks, 512 threads:
//   threadIdx = wq*128 + t  (wq = w-quarter 0..3, t = d4 lane 0..127)
// Separable weights: agg = (Σ_j ww[j,w] * colagg[j,d]) * coef[h,w]
//   colagg[j,d] = Σ_i hw[i,h] * regionsum[i*4+j,d]
//   coef[h,w]   = 0.6 / (1024 * (HS[h]*WS[w] + 1e-8))
// ---------------------------------------------------------------------------
__global__ __launch_bounds__(512) void k2_apply(const float4* __restrict__ feat,
                                                float4* __restrict__ out) {
    const int bh = blockIdx.x;
    const int b  = bh >> 7;
    const int h  = bh & 127;
    const int t  = threadIdx.x & 127;   // d4 lane
    const int wq = threadIdx.x >> 7;    // w quarter

    __shared__ float s_ww[WWD][4];
    __shared__ float s_coef[WWD];

    // per-h Gaussian weights (uniform across block, cheap)
    const float hc = h * (3.0f / 127.0f);
    float hwv[4];
    float HS = 0.f;
    #pragma unroll
    for (int i = 0; i < 4; ++i) {
        float d = hc - (float)i;
        hwv[i] = __expf(-0.125f * d * d);
        HS += hwv[i];
    }

    // per-w tables into shared (one thread per w)
    if (threadIdx.x < WWD) {
        const int w = threadIdx.x;
        const float wc = w * (3.0f / 127.0f);
        float WS = 0.f;
        #pragma unroll
        for (int j = 0; j < 4; ++j) {
            float d = wc - (float)j;
            float e = __expf(-0.125f * d * d);
            s_ww[w][j] = e;
            WS += e;
        }
        s_coef[w] = 0.6f / (1024.0f * (HS * WS + 1e-8f));
    }
    __syncthreads();

    // colagg[j] and global term for this d4 lane
    const float4* srow = g_sums + (size_t)b * 17 * DD4 + t;
    float4 ca[4];
    #pragma unroll
    for (int j = 0; j < 4; ++j) ca[j] = make_float4(0.f, 0.f, 0.f, 0.f);
    #pragma unroll
    for (int i = 0; i < 4; ++i) {
        #pragma unroll
        for (int j = 0; j < 4; ++j) {
            float4 s = srow[(i * 4 + j) * DD4];
            ca[j] = f4fma(hwv[i], s, ca[j]);
        }
    }
    float4 gs = srow[16 * DD4];
    const float gscale = 0.4f / 16384.0f;
    float4 gterm = make_float4(gs.x * gscale, gs.y * gscale, gs.z * gscale, gs.w * gscale);

    const float4* frow = feat + (size_t)bh * WWD * DD4 + t;
    float4*       orow = out  + (size_t)bh * WWD * DD4 + t;

    const int w0 = wq * 32;
    #pragma unroll 4
    for (int wi = 0; wi < 32; ++wi) {
        const int w = w0 + wi;
        float4 v = __ldg(&frow[(size_t)w * DD4]);
        const float c  = s_coef[w];
        const float b0 = s_ww[w][0] * c;
        const float b1 = s_ww[w][1] * c;
        const float b2 = s_ww[w][2] * c;
        const float b3 = s_ww[w][3] * c;

        float4 r;
        r.x = v.x + gterm.x + b0 * ca[0].x + b1 * ca[1].x + b2 * ca[2].x + b3 * ca[3].x;
        r.y = v.y + gterm.y + b0 * ca[0].y + b1 * ca[1].y + b2 * ca[2].y + b3 * ca[3].y;
        r.z = v.z + gterm.z + b0 * ca[0].z + b1 * ca[1].z + b2 * ca[2].z + b3 * ca[3].z;
        r.w = v.w + gterm.w + b0 * ca[0].w + b1 * ca[1].w + b2 * ca[2].w + b3 * ca[3].w;
        orow[(size_t)w * DD4] = r;
    }
}

// ---------------------------------------------------------------------------
extern "C" void kernel_launch(void* const* d_in, const int* in_sizes, int n_in,
                              void* d_out, int out_size) {
    const float4* feat = (const float4*)d_in[0];
    float4*       out  = (float4*)d_out;

    k1_rowsums<<<BB * HH, 128>>>(feat);
    k1b_reduce<<<BB * 17, 128>>>();
    k2_apply<<<BB * HH, 512>>>(feat, out);
}